// round 1
// baseline (speedup 1.0000x reference)
#include <cuda_runtime.h>

#define NNODES 50000
#define NEDGES 800000
#define DIN 128
#define HC 256            // H*C
#define NH 4
#define CC 64
#define NG 512
#define NOUT 10
#define NEG 0.2f
#define EPSB 1e-5f

// ---------------- scratch (static device globals; no runtime alloc) ----------
__device__ float g_h1[NNODES * HC];      // layer1 features (then reused for BN-normalized)
__device__ float g_out1[NNODES * HC];    // layer1 aggregated output
__device__ float g_h2[NNODES * CC];      // layer2 features
__device__ float g_als1[NNODES * 4];
__device__ float g_ald1[NNODES * 4];
__device__ float g_als2[NNODES];
__device__ float g_ald2[NNODES];
__device__ int   g_deg[NNODES];
__device__ int   g_rowptr[NNODES + 1];
__device__ int   g_cursor[NNODES];
__device__ int   g_csrc[NEDGES];
__device__ float g_bnsum[HC];
__device__ float g_bnsq[HC];
__device__ float g_pool[NG * CC];
__device__ float g_cnt[NG];

__device__ __forceinline__ float lrelu(float x) { return x > 0.f ? x : NEG * x; }

// ---------------- setup ------------------------------------------------------
__global__ void zero_kernel() {
    int i = blockIdx.x * blockDim.x + threadIdx.x;
    if (i < NNODES) g_deg[i] = 0;
    if (i < NG * CC) g_pool[i] = 0.f;
    if (i < NG) g_cnt[i] = 0.f;
    if (i < HC) { g_bnsum[i] = 0.f; g_bnsq[i] = 0.f; }
}

__global__ void hist_kernel(const int* __restrict__ dst) {
    int i = blockIdx.x * blockDim.x + threadIdx.x;
    if (i < NEDGES) atomicAdd(&g_deg[dst[i]], 1);
}

__global__ void scan_kernel() {
    __shared__ int sh[1024];
    __shared__ int carry;
    int tid = threadIdx.x;
    if (tid == 0) carry = 0;
    __syncthreads();
    for (int base = 0; base < NNODES; base += 1024) {
        int i = base + tid;
        int v = (i < NNODES) ? g_deg[i] : 0;
        sh[tid] = v;
        __syncthreads();
        for (int off = 1; off < 1024; off <<= 1) {
            int t = (tid >= off) ? sh[tid - off] : 0;
            __syncthreads();
            sh[tid] += t;
            __syncthreads();
        }
        int excl = carry + sh[tid] - v;
        if (i < NNODES) { g_rowptr[i] = excl; g_cursor[i] = excl; }
        __syncthreads();
        if (tid == 1023) carry += sh[1023];
        __syncthreads();
    }
    if (tid == 0) g_rowptr[NNODES] = carry;
}

__global__ void scatter_kernel(const int* __restrict__ src, const int* __restrict__ dst) {
    int i = blockIdx.x * blockDim.x + threadIdx.x;
    if (i < NEDGES) {
        int d = dst[i];
        int p = atomicAdd(&g_cursor[d], 1);
        g_csrc[p] = src[i];
    }
}

// ---------------- fp32 SIMT GEMM: C[M,Ncols] = A[M,K] @ B[K,Ncols] -----------
// BM=128, BN=64, BK=16, 256 threads, 8x4 microtile.
__global__ void __launch_bounds__(256) gemm_kernel(const float* __restrict__ A,
                                                   const float* __restrict__ B,
                                                   float* __restrict__ C,
                                                   int M, int K, int Ncols) {
    const int BM = 128, BN = 64, BK = 16;
    __shared__ float As[BK][BM];
    __shared__ float Bs[BK][BN];
    int tid = threadIdx.x;
    int tx = tid & 15, ty = tid >> 4;
    int row0 = blockIdx.y * BM;
    int n0 = blockIdx.x * BN;

    float acc[8][4];
#pragma unroll
    for (int i = 0; i < 8; i++)
#pragma unroll
        for (int j = 0; j < 4; j++) acc[i][j] = 0.f;

    for (int k0 = 0; k0 < K; k0 += BK) {
        // load A tile: 512 float4, 2 per thread
#pragma unroll
        for (int l = 0; l < 2; l++) {
            int idx = tid + l * 256;
            int r = idx >> 2, kq = idx & 3;
            float4 v = make_float4(0.f, 0.f, 0.f, 0.f);
            int gr = row0 + r;
            if (gr < M) v = *(const float4*)(A + (long)gr * K + k0 + kq * 4);
            As[kq * 4 + 0][r] = v.x;
            As[kq * 4 + 1][r] = v.y;
            As[kq * 4 + 2][r] = v.z;
            As[kq * 4 + 3][r] = v.w;
        }
        // load B tile: 256 float4, 1 per thread
        {
            int r = tid >> 4;   // k row 0..15
            int cq = tid & 15;  // 16 float4 per row
            float4 v = *(const float4*)(B + (long)(k0 + r) * Ncols + n0 + cq * 4);
            *(float4*)(&Bs[r][cq * 4]) = v;
        }
        __syncthreads();
#pragma unroll
        for (int k = 0; k < BK; k++) {
            float a[8], b[4];
            *(float4*)(a) = *(const float4*)(&As[k][ty * 8]);
            *(float4*)(a + 4) = *(const float4*)(&As[k][ty * 8 + 4]);
            *(float4*)(b) = *(const float4*)(&Bs[k][tx * 4]);
#pragma unroll
            for (int i = 0; i < 8; i++)
#pragma unroll
                for (int j = 0; j < 4; j++) acc[i][j] += a[i] * b[j];
        }
        __syncthreads();
    }
#pragma unroll
    for (int i = 0; i < 8; i++) {
        int gr = row0 + ty * 8 + i;
        if (gr < M) {
            float4 v = make_float4(acc[i][0], acc[i][1], acc[i][2], acc[i][3]);
            *(float4*)(C + (long)gr * Ncols + n0 + tx * 4) = v;
        }
    }
}

// ---------------- attention logits -------------------------------------------
__global__ void alpha1_kernel(const float* __restrict__ a_src, const float* __restrict__ a_dst) {
    int w = (blockIdx.x * blockDim.x + threadIdx.x) >> 5;
    int lane = threadIdx.x & 31;
    if (w >= NNODES) return;
    const float* hr = g_h1 + (long)w * HC;
    int c = lane * 8;
    float4 h0 = *(const float4*)(hr + c), h1v = *(const float4*)(hr + c + 4);
    float4 s0 = *(const float4*)(a_src + c), s1 = *(const float4*)(a_src + c + 4);
    float4 d0 = *(const float4*)(a_dst + c), d1 = *(const float4*)(a_dst + c + 4);
    float ps = h0.x * s0.x + h0.y * s0.y + h0.z * s0.z + h0.w * s0.w
             + h1v.x * s1.x + h1v.y * s1.y + h1v.z * s1.z + h1v.w * s1.w;
    float pd = h0.x * d0.x + h0.y * d0.y + h0.z * d0.z + h0.w * d0.w
             + h1v.x * d1.x + h1v.y * d1.y + h1v.z * d1.z + h1v.w * d1.w;
#pragma unroll
    for (int off = 4; off; off >>= 1) {
        ps += __shfl_xor_sync(0xffffffffu, ps, off);
        pd += __shfl_xor_sync(0xffffffffu, pd, off);
    }
    if ((lane & 7) == 0) {
        g_als1[w * 4 + (lane >> 3)] = ps;
        g_ald1[w * 4 + (lane >> 3)] = pd;
    }
}

__global__ void alpha2_kernel(const float* __restrict__ a_src, const float* __restrict__ a_dst) {
    int w = (blockIdx.x * blockDim.x + threadIdx.x) >> 5;
    int lane = threadIdx.x & 31;
    if (w >= NNODES) return;
    const float* hr = g_h2 + (long)w * CC;
    int c = lane * 2;
    float2 h = *(const float2*)(hr + c);
    float2 sa = *(const float2*)(a_src + c);
    float2 da = *(const float2*)(a_dst + c);
    float ps = h.x * sa.x + h.y * sa.y;
    float pd = h.x * da.x + h.y * da.y;
#pragma unroll
    for (int off = 16; off; off >>= 1) {
        ps += __shfl_xor_sync(0xffffffffu, ps, off);
        pd += __shfl_xor_sync(0xffffffffu, pd, off);
    }
    if (lane == 0) { g_als2[w] = ps; g_ald2[w] = pd; }
}

// ---------------- layer-1 edge softmax + aggregation (warp per dst node) -----
__global__ void __launch_bounds__(256) edge1_kernel(const float* __restrict__ b1) {
    int w = (blockIdx.x * blockDim.x + threadIdx.x) >> 5;
    if (w >= NNODES) return;
    int lane = threadIdx.x & 31;
    int rs = g_rowptr[w], re = g_rowptr[w + 1];
    float4 ad = *(const float4*)(g_ald1 + 4 * w);
    float4 as = *(const float4*)(g_als1 + 4 * w);
    // pass 1: per-head max (init with self-loop)
    float m0 = lrelu(as.x + ad.x);
    float m1 = lrelu(as.y + ad.y);
    float m2 = lrelu(as.z + ad.z);
    float m3 = lrelu(as.w + ad.w);
    for (int i = rs + lane; i < re; i += 32) {
        int s = g_csrc[i];
        float4 a = *(const float4*)(g_als1 + 4 * s);
        m0 = fmaxf(m0, lrelu(a.x + ad.x));
        m1 = fmaxf(m1, lrelu(a.y + ad.y));
        m2 = fmaxf(m2, lrelu(a.z + ad.z));
        m3 = fmaxf(m3, lrelu(a.w + ad.w));
    }
#pragma unroll
    for (int off = 16; off; off >>= 1) {
        m0 = fmaxf(m0, __shfl_xor_sync(0xffffffffu, m0, off));
        m1 = fmaxf(m1, __shfl_xor_sync(0xffffffffu, m1, off));
        m2 = fmaxf(m2, __shfl_xor_sync(0xffffffffu, m2, off));
        m3 = fmaxf(m3, __shfl_xor_sync(0xffffffffu, m3, off));
    }
    int head = lane >> 3;  // channels lane*8..lane*8+7 all belong to this head
    float adh = (head == 0) ? ad.x : (head == 1) ? ad.y : (head == 2) ? ad.z : ad.w;
    float mh  = (head == 0) ? m0  : (head == 1) ? m1  : (head == 2) ? m2  : m3;
    // pass 2: serial over edges (+ self as last), accumulate exp(e-m)*h, track z
    float z = 0.f;
    float acc[8];
#pragma unroll
    for (int q = 0; q < 8; q++) acc[q] = 0.f;
    const float* __restrict__ H = g_h1;
    for (int i = rs; i <= re; ++i) {
        int s = (i < re) ? g_csrc[i] : w;
        float e = g_als1[4 * s + head] + adh;
        e = e > 0.f ? e : NEG * e;
        float wt = __expf(e - mh);
        z += wt;
        const float4* hp = (const float4*)(H + (long)s * HC + lane * 8);
        float4 h0 = hp[0], h1v = hp[1];
        acc[0] += wt * h0.x;  acc[1] += wt * h0.y;
        acc[2] += wt * h0.z;  acc[3] += wt * h0.w;
        acc[4] += wt * h1v.x; acc[5] += wt * h1v.y;
        acc[6] += wt * h1v.z; acc[7] += wt * h1v.w;
    }
    float inv = 1.f / (z + 1e-16f);
    int c = lane * 8;
    float4 o0 = make_float4(acc[0] * inv + b1[c],     acc[1] * inv + b1[c + 1],
                            acc[2] * inv + b1[c + 2], acc[3] * inv + b1[c + 3]);
    float4 o1 = make_float4(acc[4] * inv + b1[c + 4], acc[5] * inv + b1[c + 5],
                            acc[6] * inv + b1[c + 6], acc[7] * inv + b1[c + 7]);
    *(float4*)(g_out1 + (long)w * HC + c) = o0;
    *(float4*)(g_out1 + (long)w * HC + c + 4) = o1;
}

// ---------------- batchnorm --------------------------------------------------
__global__ void bn_stats_kernel() {
    int c = threadIdx.x;  // 256 threads = 256 features
    float s = 0.f, q = 0.f;
    for (int r = blockIdx.x; r < NNODES; r += gridDim.x) {
        float v = g_out1[(long)r * HC + c];
        s += v;
        q += v * v;
    }
    atomicAdd(&g_bnsum[c], s);
    atomicAdd(&g_bnsq[c], q);
}

__global__ void bn_apply_kernel(const float* __restrict__ gamma, const float* __restrict__ beta) {
    int i = blockIdx.x * blockDim.x + threadIdx.x;  // float4 index
    if (i >= NNODES * HC / 4) return;
    int c = (i & 63) * 4;  // HC/4 = 64 float4 per row
    float4 v = *(const float4*)(g_out1 + (long)i * 4);
    float invN = 1.f / (float)NNODES;
    float o[4] = {v.x, v.y, v.z, v.w};
#pragma unroll
    for (int j = 0; j < 4; j++) {
        float mean = g_bnsum[c + j] * invN;
        float var = g_bnsq[c + j] * invN - mean * mean;
        float t = (o[j] - mean) * rsqrtf(var + EPSB) * gamma[c + j] + beta[c + j];
        o[j] = t > 0.f ? t : 0.f;
    }
    *(float4*)(g_h1 + (long)i * 4) = make_float4(o[0], o[1], o[2], o[3]);
}

// ---------------- layer-2 edge softmax + aggregation + pool ------------------
__global__ void __launch_bounds__(256) edge2_kernel(const float* __restrict__ b2,
                                                    const int* __restrict__ batch) {
    int w = (blockIdx.x * blockDim.x + threadIdx.x) >> 5;
    if (w >= NNODES) return;
    int lane = threadIdx.x & 31;
    int rs = g_rowptr[w], re = g_rowptr[w + 1];
    float ald = g_ald2[w];
    float m = lrelu(g_als2[w] + ald);  // self-loop
    for (int i = rs + lane; i < re; i += 32)
        m = fmaxf(m, lrelu(g_als2[g_csrc[i]] + ald));
#pragma unroll
    for (int off = 16; off; off >>= 1)
        m = fmaxf(m, __shfl_xor_sync(0xffffffffu, m, off));
    float z = 0.f, a0 = 0.f, a1 = 0.f;
    for (int i = rs; i <= re; ++i) {
        int s = (i < re) ? g_csrc[i] : w;
        float e = g_als2[s] + ald;
        e = e > 0.f ? e : NEG * e;
        float wt = __expf(e - m);
        z += wt;
        float2 h = *(const float2*)(g_h2 + (long)s * CC + lane * 2);
        a0 += wt * h.x;
        a1 += wt * h.y;
    }
    float inv = 1.f / (z + 1e-16f);
    int c = lane * 2;
    float v0 = fmaxf(a0 * inv + b2[c], 0.f);
    float v1 = fmaxf(a1 * inv + b2[c + 1], 0.f);
    int g = batch[w];
    atomicAdd(&g_pool[g * CC + c], v0);
    atomicAdd(&g_pool[g * CC + c + 1], v1);
    if (lane == 0) atomicAdd(&g_cnt[g], 1.f);
}

// ---------------- classifier -------------------------------------------------
__global__ void cls_kernel(const float* __restrict__ cW1, const float* __restrict__ cb1,
                           const float* __restrict__ cW2, const float* __restrict__ cb2,
                           float* __restrict__ out) {
    int g = blockIdx.x;
    __shared__ float p[CC];
    __shared__ float hid[CC / 2];
    int t = threadIdx.x;  // 64 threads
    float cnt = fmaxf(g_cnt[g], 1.f);
    p[t] = g_pool[g * CC + t] / cnt;
    __syncthreads();
    if (t < 32) {
        float s = cb1[t];
#pragma unroll
        for (int c = 0; c < CC; c++) s += p[c] * cW1[c * 32 + t];
        hid[t] = fmaxf(s, 0.f);
    }
    __syncthreads();
    if (t < NOUT) {
        float s = cb2[t];
#pragma unroll
        for (int j = 0; j < 32; j++) s += hid[j] * cW2[j * NOUT + t];
        out[g * NOUT + t] = s;
    }
}

// ---------------- launch -----------------------------------------------------
extern "C" void kernel_launch(void* const* d_in, const int* in_sizes, int n_in,
                              void* d_out, int out_size) {
    const float* x     = (const float*)d_in[0];
    const int*   ei    = (const int*)d_in[1];
    const int*   batch = (const int*)d_in[2];
    const float* W1    = (const float*)d_in[3];
    const float* as1   = (const float*)d_in[4];
    const float* ad1   = (const float*)d_in[5];
    const float* b1    = (const float*)d_in[6];
    const float* gamma = (const float*)d_in[7];
    const float* beta  = (const float*)d_in[8];
    const float* W2    = (const float*)d_in[9];
    const float* as2   = (const float*)d_in[10];
    const float* ad2   = (const float*)d_in[11];
    const float* b2    = (const float*)d_in[12];
    const float* cW1   = (const float*)d_in[13];
    const float* cb1   = (const float*)d_in[14];
    const float* cW2   = (const float*)d_in[15];
    const float* cb2   = (const float*)d_in[16];
    float* out = (float*)d_out;

    const int* src = ei;
    const int* dst = ei + NEDGES;

    float *h1p, *h2p;
    cudaGetSymbolAddress((void**)&h1p, g_h1);
    cudaGetSymbolAddress((void**)&h2p, g_h2);

    const int EB = (NEDGES + 255) / 256;
    const int WB = (NNODES * 32 + 255) / 256;  // warp-per-node kernels

    zero_kernel<<<(NNODES + 255) / 256, 256>>>();
    hist_kernel<<<EB, 256>>>(dst);
    scan_kernel<<<1, 1024>>>();
    scatter_kernel<<<EB, 256>>>(src, dst);

    // layer 1
    gemm_kernel<<<dim3(HC / 64, (NNODES + 127) / 128), 256>>>(x, W1, h1p, NNODES, DIN, HC);
    alpha1_kernel<<<WB, 256>>>(as1, ad1);
    edge1_kernel<<<WB, 256>>>(b1);
    bn_stats_kernel<<<256, 256>>>();
    bn_apply_kernel<<<(NNODES * HC / 4 + 255) / 256, 256>>>(gamma, beta);

    // layer 2
    gemm_kernel<<<dim3(CC / 64, (NNODES + 127) / 128), 256>>>(h1p, W2, h2p, NNODES, HC, CC);
    alpha2_kernel<<<WB, 256>>>(as2, ad2);
    edge2_kernel<<<WB, 256>>>(b2, batch);

    // classifier
    cls_kernel<<<NG, 64>>>(cW1, cb1, cW2, cb2, out);
}

// round 4
// speedup vs baseline: 1.3304x; 1.3304x over previous
#include <cuda_runtime.h>
#include <cuda_fp16.h>

#define NNODES 50000
#define NEDGES 800000
#define DIN 128
#define HC 256            // H*C
#define NH 4
#define CC 64
#define NG 512
#define NOUT 10
#define NEG 0.2f
#define EPSB 1e-5f
#define NB_SCAN 49        // ceil(50000/1024)

// ---------------- scratch (static device globals; no runtime alloc) ----------
__device__ float  g_h1[NNODES * HC];     // BN-normalized layer1 output (GEMM2 input, fp32)
__device__ __half g_h1h[NNODES * HC];    // GEMM1 output (fp16, gather source)
__device__ float  g_out1[NNODES * HC];   // layer1 aggregated output (fp32)
__device__ __half g_h2h[NNODES * CC];    // GEMM2 output (fp16, gather source)
__device__ float g_als1[NNODES * 4];
__device__ float g_ald1[NNODES * 4];
__device__ float g_als2[NNODES];
__device__ float g_ald2[NNODES];
__device__ int   g_deg[NNODES];
__device__ int   g_rowptr[NNODES + 1];
__device__ int   g_cursor[NNODES];
__device__ int   g_csrc[NEDGES];
__device__ int   g_blksum[NB_SCAN];
__device__ float g_bnsum[HC];
__device__ float g_bnsq[HC];
__device__ float g_pool[NG * CC];
__device__ float g_cnt[NG];

__device__ __forceinline__ float lrelu(float x) { return x > 0.f ? x : NEG * x; }

// ---------------- setup ------------------------------------------------------
__global__ void zero_kernel() {
    int i = blockIdx.x * blockDim.x + threadIdx.x;
    if (i < NNODES) g_deg[i] = 0;
    if (i < NG * CC) g_pool[i] = 0.f;
    if (i < NG) g_cnt[i] = 0.f;
    if (i < HC) { g_bnsum[i] = 0.f; g_bnsq[i] = 0.f; }
}

__global__ void hist_kernel(const int* __restrict__ dst) {
    int i = blockIdx.x * blockDim.x + threadIdx.x;
    if (i * 4 < NEDGES) {
        int4 d = ((const int4*)dst)[i];
        atomicAdd(&g_deg[d.x], 1);
        atomicAdd(&g_deg[d.y], 1);
        atomicAdd(&g_deg[d.z], 1);
        atomicAdd(&g_deg[d.w], 1);
    }
}

// 3-phase exclusive scan over g_deg -> g_rowptr
__global__ void __launch_bounds__(1024) scanA_kernel() {
    __shared__ int warp_sums[32];
    int tid = threadIdx.x;
    int i = blockIdx.x * 1024 + tid;
    int lane = tid & 31, wid = tid >> 5;
    int v = (i < NNODES) ? g_deg[i] : 0;
    int incl = v;
#pragma unroll
    for (int off = 1; off < 32; off <<= 1) {
        int t = __shfl_up_sync(0xffffffffu, incl, off);
        if (lane >= off) incl += t;
    }
    if (lane == 31) warp_sums[wid] = incl;
    __syncthreads();
    if (wid == 0) {
        int s = warp_sums[lane];
#pragma unroll
        for (int off = 1; off < 32; off <<= 1) {
            int t = __shfl_up_sync(0xffffffffu, s, off);
            if (lane >= off) s += t;
        }
        warp_sums[lane] = s;
    }
    __syncthreads();
    int woff = (wid > 0) ? warp_sums[wid - 1] : 0;
    if (i < NNODES) g_rowptr[i] = woff + incl - v;
    if (tid == 1023) g_blksum[blockIdx.x] = woff + incl;
}

__global__ void scanB_kernel() {
    if (threadIdx.x == 0) {
        int acc = 0;
#pragma unroll
        for (int b = 0; b < NB_SCAN; b++) {
            int t = g_blksum[b];
            g_blksum[b] = acc;
            acc += t;
        }
        g_rowptr[NNODES] = acc;
    }
}

__global__ void __launch_bounds__(1024) scanC_kernel() {
    int i = blockIdx.x * 1024 + threadIdx.x;
    if (i < NNODES) {
        int r = g_rowptr[i] + g_blksum[blockIdx.x];
        g_rowptr[i] = r;
        g_cursor[i] = r;
    }
}

__global__ void scatter_kernel(const int* __restrict__ src, const int* __restrict__ dst) {
    int i = blockIdx.x * blockDim.x + threadIdx.x;
    if (i * 4 < NEDGES) {
        int4 s = ((const int4*)src)[i];
        int4 d = ((const int4*)dst)[i];
        g_csrc[atomicAdd(&g_cursor[d.x], 1)] = s.x;
        g_csrc[atomicAdd(&g_cursor[d.y], 1)] = s.y;
        g_csrc[atomicAdd(&g_cursor[d.z], 1)] = s.z;
        g_csrc[atomicAdd(&g_cursor[d.w], 1)] = s.w;
    }
}

// ---------------- fp32 SIMT GEMM: C[M,Ncols] = A[M,K] @ B[K,Ncols] -----------
// BM=128, BN=64, BK=16, 256 threads, 8x4 microtile. Epilogue: half or float.
__global__ void __launch_bounds__(256) gemm_kernel(const float* __restrict__ A,
                                                   const float* __restrict__ B,
                                                   float* __restrict__ Cf,
                                                   __half* __restrict__ Ch,
                                                   int M, int K, int Ncols) {
    const int BM = 128, BN = 64, BK = 16;
    __shared__ float As[BK][BM];
    __shared__ float Bs[BK][BN];
    int tid = threadIdx.x;
    int tx = tid & 15, ty = tid >> 4;
    int row0 = blockIdx.y * BM;
    int n0 = blockIdx.x * BN;

    float acc[8][4];
#pragma unroll
    for (int i = 0; i < 8; i++)
#pragma unroll
        for (int j = 0; j < 4; j++) acc[i][j] = 0.f;

    for (int k0 = 0; k0 < K; k0 += BK) {
#pragma unroll
        for (int l = 0; l < 2; l++) {
            int idx = tid + l * 256;
            int r = idx >> 2, kq = idx & 3;
            float4 v = make_float4(0.f, 0.f, 0.f, 0.f);
            int gr = row0 + r;
            if (gr < M) v = *(const float4*)(A + (long)gr * K + k0 + kq * 4);
            As[kq * 4 + 0][r] = v.x;
            As[kq * 4 + 1][r] = v.y;
            As[kq * 4 + 2][r] = v.z;
            As[kq * 4 + 3][r] = v.w;
        }
        {
            int r = tid >> 4;
            int cq = tid & 15;
            float4 v = *(const float4*)(B + (long)(k0 + r) * Ncols + n0 + cq * 4);
            *(float4*)(&Bs[r][cq * 4]) = v;
        }
        __syncthreads();
#pragma unroll
        for (int k = 0; k < BK; k++) {
            float a[8], b[4];
            *(float4*)(a) = *(const float4*)(&As[k][ty * 8]);
            *(float4*)(a + 4) = *(const float4*)(&As[k][ty * 8 + 4]);
            *(float4*)(b) = *(const float4*)(&Bs[k][tx * 4]);
#pragma unroll
            for (int i = 0; i < 8; i++)
#pragma unroll
                for (int j = 0; j < 4; j++) acc[i][j] += a[i] * b[j];
        }
        __syncthreads();
    }
#pragma unroll
    for (int i = 0; i < 8; i++) {
        int gr = row0 + ty * 8 + i;
        if (gr < M) {
            if (Ch) {
                __half2 p0 = __floats2half2_rn(acc[i][0], acc[i][1]);
                __half2 p1 = __floats2half2_rn(acc[i][2], acc[i][3]);
                uint2 u = make_uint2(*(unsigned*)&p0, *(unsigned*)&p1);
                *(uint2*)(Ch + (long)gr * Ncols + n0 + tx * 4) = u;
            } else {
                float4 v = make_float4(acc[i][0], acc[i][1], acc[i][2], acc[i][3]);
                *(float4*)(Cf + (long)gr * Ncols + n0 + tx * 4) = v;
            }
        }
    }
}

// ---------------- attention logits -------------------------------------------
__global__ void alpha1_kernel(const float* __restrict__ a_src, const float* __restrict__ a_dst) {
    int w = (blockIdx.x * blockDim.x + threadIdx.x) >> 5;
    int lane = threadIdx.x & 31;
    if (w >= NNODES) return;
    int c = lane * 8;
    uint4 u = *(const uint4*)(g_h1h + (long)w * HC + c);
    float2 f0 = __half22float2(*(__half2*)&u.x);
    float2 f1 = __half22float2(*(__half2*)&u.y);
    float2 f2 = __half22float2(*(__half2*)&u.z);
    float2 f3 = __half22float2(*(__half2*)&u.w);
    float4 s0 = *(const float4*)(a_src + c), s1 = *(const float4*)(a_src + c + 4);
    float4 d0 = *(const float4*)(a_dst + c), d1 = *(const float4*)(a_dst + c + 4);
    float ps = f0.x * s0.x + f0.y * s0.y + f1.x * s0.z + f1.y * s0.w
             + f2.x * s1.x + f2.y * s1.y + f3.x * s1.z + f3.y * s1.w;
    float pd = f0.x * d0.x + f0.y * d0.y + f1.x * d0.z + f1.y * d0.w
             + f2.x * d1.x + f2.y * d1.y + f3.x * d1.z + f3.y * d1.w;
#pragma unroll
    for (int off = 4; off; off >>= 1) {
        ps += __shfl_xor_sync(0xffffffffu, ps, off);
        pd += __shfl_xor_sync(0xffffffffu, pd, off);
    }
    if ((lane & 7) == 0) {
        g_als1[w * 4 + (lane >> 3)] = ps;
        g_ald1[w * 4 + (lane >> 3)] = pd;
    }
}

__global__ void alpha2_kernel(const float* __restrict__ a_src, const float* __restrict__ a_dst) {
    int w = (blockIdx.x * blockDim.x + threadIdx.x) >> 5;
    int lane = threadIdx.x & 31;
    if (w >= NNODES) return;
    int c = lane * 2;
    float2 h = __half22float2(*(const __half2*)(g_h2h + (long)w * CC + c));
    float2 sa = *(const float2*)(a_src + c);
    float2 da = *(const float2*)(a_dst + c);
    float ps = h.x * sa.x + h.y * sa.y;
    float pd = h.x * da.x + h.y * da.y;
#pragma unroll
    for (int off = 16; off; off >>= 1) {
        ps += __shfl_xor_sync(0xffffffffu, ps, off);
        pd += __shfl_xor_sync(0xffffffffu, pd, off);
    }
    if (lane == 0) { g_als2[w] = ps; g_ald2[w] = pd; }
}

// ---------------- layer-1 edge softmax + aggregation (warp per dst node) -----
__global__ void __launch_bounds__(256) edge1_kernel(const float* __restrict__ b1) {
    int w = (blockIdx.x * blockDim.x + threadIdx.x) >> 5;
    if (w >= NNODES) return;
    int lane = threadIdx.x & 31;
    int rs = g_rowptr[w], re = g_rowptr[w + 1];
    float4 ad = *(const float4*)(g_ald1 + 4 * w);
    float4 as = *(const float4*)(g_als1 + 4 * w);
    float m0 = lrelu(as.x + ad.x);
    float m1 = lrelu(as.y + ad.y);
    float m2 = lrelu(as.z + ad.z);
    float m3 = lrelu(as.w + ad.w);
    for (int i = rs + lane; i < re; i += 32) {
        int s = g_csrc[i];
        float4 a = *(const float4*)(g_als1 + 4 * s);
        m0 = fmaxf(m0, lrelu(a.x + ad.x));
        m1 = fmaxf(m1, lrelu(a.y + ad.y));
        m2 = fmaxf(m2, lrelu(a.z + ad.z));
        m3 = fmaxf(m3, lrelu(a.w + ad.w));
    }
#pragma unroll
    for (int off = 16; off; off >>= 1) {
        m0 = fmaxf(m0, __shfl_xor_sync(0xffffffffu, m0, off));
        m1 = fmaxf(m1, __shfl_xor_sync(0xffffffffu, m1, off));
        m2 = fmaxf(m2, __shfl_xor_sync(0xffffffffu, m2, off));
        m3 = fmaxf(m3, __shfl_xor_sync(0xffffffffu, m3, off));
    }
    int head = lane >> 3;
    float adh = (head == 0) ? ad.x : (head == 1) ? ad.y : (head == 2) ? ad.z : ad.w;
    float mh  = (head == 0) ? m0  : (head == 1) ? m1  : (head == 2) ? m2  : m3;
    float z = 0.f;
    float acc[8];
#pragma unroll
    for (int q = 0; q < 8; q++) acc[q] = 0.f;
    for (int i = rs; i <= re; ++i) {
        int s = (i < re) ? g_csrc[i] : w;
        float e = g_als1[4 * s + head] + adh;
        e = e > 0.f ? e : NEG * e;
        float wt = __expf(e - mh);
        z += wt;
        uint4 u = *(const uint4*)(g_h1h + (long)s * HC + lane * 8);
        float2 f0 = __half22float2(*(__half2*)&u.x);
        float2 f1 = __half22float2(*(__half2*)&u.y);
        float2 f2 = __half22float2(*(__half2*)&u.z);
        float2 f3 = __half22float2(*(__half2*)&u.w);
        acc[0] += wt * f0.x;  acc[1] += wt * f0.y;
        acc[2] += wt * f1.x;  acc[3] += wt * f1.y;
        acc[4] += wt * f2.x;  acc[5] += wt * f2.y;
        acc[6] += wt * f3.x;  acc[7] += wt * f3.y;
    }
    float inv = 1.f / (z + 1e-16f);
    int c = lane * 8;
    float4 o0 = make_float4(acc[0] * inv + b1[c],     acc[1] * inv + b1[c + 1],
                            acc[2] * inv + b1[c + 2], acc[3] * inv + b1[c + 3]);
    float4 o1 = make_float4(acc[4] * inv + b1[c + 4], acc[5] * inv + b1[c + 5],
                            acc[6] * inv + b1[c + 6], acc[7] * inv + b1[c + 7]);
    *(float4*)(g_out1 + (long)w * HC + c) = o0;
    *(float4*)(g_out1 + (long)w * HC + c + 4) = o1;
}

// ---------------- batchnorm --------------------------------------------------
__global__ void bn_stats_kernel() {
    int c = threadIdx.x;
    float s = 0.f, q = 0.f;
    for (int r = blockIdx.x; r < NNODES; r += gridDim.x) {
        float v = g_out1[(long)r * HC + c];
        s += v;
        q += v * v;
    }
    atomicAdd(&g_bnsum[c], s);
    atomicAdd(&g_bnsq[c], q);
}

__global__ void bn_apply_kernel(const float* __restrict__ gamma, const float* __restrict__ beta) {
    int i = blockIdx.x * blockDim.x + threadIdx.x;
    if (i >= NNODES * HC / 4) return;
    int c = (i & 63) * 4;
    float4 v = *(const float4*)(g_out1 + (long)i * 4);
    float invN = 1.f / (float)NNODES;
    float o[4] = {v.x, v.y, v.z, v.w};
#pragma unroll
    for (int j = 0; j < 4; j++) {
        float mean = g_bnsum[c + j] * invN;
        float var = g_bnsq[c + j] * invN - mean * mean;
        float t = (o[j] - mean) * rsqrtf(var + EPSB) * gamma[c + j] + beta[c + j];
        o[j] = t > 0.f ? t : 0.f;
    }
    *(float4*)(g_h1 + (long)i * 4) = make_float4(o[0], o[1], o[2], o[3]);
}

// ---------------- layer-2 edge softmax + aggregation + pool ------------------
__global__ void __launch_bounds__(256) edge2_kernel(const float* __restrict__ b2,
                                                    const int* __restrict__ batch) {
    int w = (blockIdx.x * blockDim.x + threadIdx.x) >> 5;
    if (w >= NNODES) return;
    int lane = threadIdx.x & 31;
    int rs = g_rowptr[w], re = g_rowptr[w + 1];
    float ald = g_ald2[w];
    float m = lrelu(g_als2[w] + ald);
    for (int i = rs + lane; i < re; i += 32)
        m = fmaxf(m, lrelu(g_als2[g_csrc[i]] + ald));
#pragma unroll
    for (int off = 16; off; off >>= 1)
        m = fmaxf(m, __shfl_xor_sync(0xffffffffu, m, off));
    float z = 0.f, a0 = 0.f, a1 = 0.f;
    for (int i = rs; i <= re; ++i) {
        int s = (i < re) ? g_csrc[i] : w;
        float e = g_als2[s] + ald;
        e = e > 0.f ? e : NEG * e;
        float wt = __expf(e - m);
        z += wt;
        float2 h = __half22float2(*(const __half2*)(g_h2h + (long)s * CC + lane * 2));
        a0 += wt * h.x;
        a1 += wt * h.y;
    }
    float inv = 1.f / (z + 1e-16f);
    int c = lane * 2;
    float v0 = fmaxf(a0 * inv + b2[c], 0.f);
    float v1 = fmaxf(a1 * inv + b2[c + 1], 0.f);
    int g = batch[w];
    atomicAdd(&g_pool[g * CC + c], v0);
    atomicAdd(&g_pool[g * CC + c + 1], v1);
    if (lane == 0) atomicAdd(&g_cnt[g], 1.f);
}

// ---------------- classifier -------------------------------------------------
__global__ void cls_kernel(const float* __restrict__ cW1, const float* __restrict__ cb1,
                           const float* __restrict__ cW2, const float* __restrict__ cb2,
                           float* __restrict__ out) {
    int g = blockIdx.x;
    __shared__ float p[CC];
    __shared__ float hid[CC / 2];
    int t = threadIdx.x;
    float cnt = fmaxf(g_cnt[g], 1.f);
    p[t] = g_pool[g * CC + t] / cnt;
    __syncthreads();
    if (t < 32) {
        float s = cb1[t];
#pragma unroll
        for (int c = 0; c < CC; c++) s += p[c] * cW1[c * 32 + t];
        hid[t] = fmaxf(s, 0.f);
    }
    __syncthreads();
    if (t < NOUT) {
        float s = cb2[t];
#pragma unroll
        for (int j = 0; j < 32; j++) s += hid[j] * cW2[j * NOUT + t];
        out[g * NOUT + t] = s;
    }
}

// ---------------- launch -----------------------------------------------------
extern "C" void kernel_launch(void* const* d_in, const int* in_sizes, int n_in,
                              void* d_out, int out_size) {
    const float* x     = (const float*)d_in[0];
    const int*   ei    = (const int*)d_in[1];
    const int*   batch = (const int*)d_in[2];
    const float* W1    = (const float*)d_in[3];
    const float* as1   = (const float*)d_in[4];
    const float* ad1   = (const float*)d_in[5];
    const float* b1    = (const float*)d_in[6];
    const float* gamma = (const float*)d_in[7];
    const float* beta  = (const float*)d_in[8];
    const float* W2    = (const float*)d_in[9];
    const float* as2   = (const float*)d_in[10];
    const float* ad2   = (const float*)d_in[11];
    const float* b2    = (const float*)d_in[12];
    const float* cW1   = (const float*)d_in[13];
    const float* cb1   = (const float*)d_in[14];
    const float* cW2   = (const float*)d_in[15];
    const float* cb2   = (const float*)d_in[16];
    float* out = (float*)d_out;

    const int* src = ei;
    const int* dst = ei + NEDGES;

    float *h1p;
    __half *h1hp, *h2hp;
    cudaGetSymbolAddress((void**)&h1p, g_h1);
    cudaGetSymbolAddress((void**)&h1hp, g_h1h);
    cudaGetSymbolAddress((void**)&h2hp, g_h2h);

    const int EB4 = (NEDGES / 4 + 255) / 256;
    const int WB = (NNODES * 32 + 255) / 256;

    zero_kernel<<<(NNODES + 255) / 256, 256>>>();
    hist_kernel<<<EB4, 256>>>(dst);
    scanA_kernel<<<NB_SCAN, 1024>>>();
    scanB_kernel<<<1, 32>>>();
    scanC_kernel<<<NB_SCAN, 1024>>>();
    scatter_kernel<<<EB4, 256>>>(src, dst);

    // layer 1
    gemm_kernel<<<dim3(HC / 64, (NNODES + 127) / 128), 256>>>(x, W1, nullptr, h1hp, NNODES, DIN, HC);
    alpha1_kernel<<<WB, 256>>>(as1, ad1);
    edge1_kernel<<<WB, 256>>>(b1);
    bn_stats_kernel<<<256, 256>>>();
    bn_apply_kernel<<<(NNODES * HC / 4 + 255) / 256, 256>>>(gamma, beta);

    // layer 2
    gemm_kernel<<<dim3(CC / 64, (NNODES + 127) / 128), 256>>>(h1p, W2, nullptr, h2hp, NNODES, HC, CC);
    alpha2_kernel<<<WB, 256>>>(as2, ad2);
    edge2_kernel<<<WB, 256>>>(b2, batch);

    // classifier
    cls_kernel<<<NG, 64>>>(cW1, cb1, cW2, cb2, out);
}

// round 6
// speedup vs baseline: 1.6933x; 1.2727x over previous
#include <cuda_runtime.h>
#include <cuda_fp16.h>
#include <mma.h>
using namespace nvcuda;

#define NNODES 50000
#define NEDGES 800000
#define DIN 128
#define HC 256            // H*C
#define NH 4
#define CC 64
#define NG 512
#define NOUT 10
#define NEG 0.2f
#define EPSB 1e-5f
#define NB_SCAN 49        // ceil(50000/1024)

// ---------------- scratch (static device globals; no runtime alloc) ----------
__device__ float  g_h1[NNODES * HC];     // BN-normalized layer1 output (GEMM2 input, fp32)
__device__ __half g_h1h[NNODES * HC];    // GEMM1 output (fp16, gather source)
__device__ float  g_out1[NNODES * HC];   // layer1 aggregated output (fp32)
__device__ __half g_h2h[NNODES * CC];    // GEMM2 output (fp16, gather source)
__device__ float g_als1[NNODES * 4];
__device__ float g_ald1[NNODES * 4];
__device__ float g_als2[NNODES];
__device__ float g_ald2[NNODES];
__device__ int   g_deg[NNODES];
__device__ int   g_rowptr[NNODES + 1];
__device__ int   g_cursor[NNODES];
__device__ int   g_csrc[NEDGES];
__device__ int   g_blksum[NB_SCAN];
__device__ float g_bnsum[HC];
__device__ float g_bnsq[HC];
__device__ float g_pool[NG * CC];
__device__ float g_cnt[NG];

__device__ __forceinline__ float lrelu(float x) { return x > 0.f ? x : NEG * x; }

// ---------------- setup ------------------------------------------------------
__global__ void zero_kernel() {
    int i = blockIdx.x * blockDim.x + threadIdx.x;
    if (i < NNODES) g_deg[i] = 0;
    if (i < NG * CC) g_pool[i] = 0.f;
    if (i < NG) g_cnt[i] = 0.f;
    if (i < HC) { g_bnsum[i] = 0.f; g_bnsq[i] = 0.f; }
}

__global__ void hist_kernel(const int* __restrict__ dst) {
    int i = blockIdx.x * blockDim.x + threadIdx.x;
    if (i * 4 < NEDGES) {
        int4 d = ((const int4*)dst)[i];
        atomicAdd(&g_deg[d.x], 1);
        atomicAdd(&g_deg[d.y], 1);
        atomicAdd(&g_deg[d.z], 1);
        atomicAdd(&g_deg[d.w], 1);
    }
}

// 3-phase exclusive scan over g_deg -> g_rowptr
__global__ void __launch_bounds__(1024) scanA_kernel() {
    __shared__ int warp_sums[32];
    int tid = threadIdx.x;
    int i = blockIdx.x * 1024 + tid;
    int lane = tid & 31, wid = tid >> 5;
    int v = (i < NNODES) ? g_deg[i] : 0;
    int incl = v;
#pragma unroll
    for (int off = 1; off < 32; off <<= 1) {
        int t = __shfl_up_sync(0xffffffffu, incl, off);
        if (lane >= off) incl += t;
    }
    if (lane == 31) warp_sums[wid] = incl;
    __syncthreads();
    if (wid == 0) {
        int s = warp_sums[lane];
#pragma unroll
        for (int off = 1; off < 32; off <<= 1) {
            int t = __shfl_up_sync(0xffffffffu, s, off);
            if (lane >= off) s += t;
        }
        warp_sums[lane] = s;
    }
    __syncthreads();
    int woff = (wid > 0) ? warp_sums[wid - 1] : 0;
    if (i < NNODES) g_rowptr[i] = woff + incl - v;
    if (tid == 1023) g_blksum[blockIdx.x] = woff + incl;
}

__global__ void scanB_kernel() {
    int lane = threadIdx.x;  // 32 threads, warp-parallel scan of 49 block sums
    int acc = 0;
    for (int base = 0; base < NB_SCAN; base += 32) {
        int idx = base + lane;
        int v = (idx < NB_SCAN) ? g_blksum[idx] : 0;
        int incl = v;
#pragma unroll
        for (int off = 1; off < 32; off <<= 1) {
            int t = __shfl_up_sync(0xffffffffu, incl, off);
            if (lane >= off) incl += t;
        }
        if (idx < NB_SCAN) g_blksum[idx] = acc + incl - v;
        acc += __shfl_sync(0xffffffffu, incl, 31);
    }
    if (lane == 0) g_rowptr[NNODES] = acc;
}

__global__ void __launch_bounds__(1024) scanC_kernel() {
    int i = blockIdx.x * 1024 + threadIdx.x;
    if (i < NNODES) {
        int r = g_rowptr[i] + g_blksum[blockIdx.x];
        g_rowptr[i] = r;
        g_cursor[i] = r;
    }
}

__global__ void scatter_kernel(const int* __restrict__ src, const int* __restrict__ dst) {
    int i = blockIdx.x * blockDim.x + threadIdx.x;
    if (i * 4 < NEDGES) {
        int4 s = ((const int4*)src)[i];
        int4 d = ((const int4*)dst)[i];
        g_csrc[atomicAdd(&g_cursor[d.x], 1)] = s.x;
        g_csrc[atomicAdd(&g_cursor[d.y], 1)] = s.y;
        g_csrc[atomicAdd(&g_cursor[d.z], 1)] = s.z;
        g_csrc[atomicAdd(&g_cursor[d.w], 1)] = s.w;
    }
}

// ---------------- tensor-core GEMM: C[M,N] = A[M,K] @ B[K,N] -----------------
// fp32 inputs converted to fp16 at tile-load, fp32 accumulate, fp16 output.
// BM=128, BN=64, BK=32; 256 threads = 8 warps (4x2), warp tile 32x32.
#define GBM 128
#define GBN 64
#define GBK 32

__global__ void __launch_bounds__(256) gemm_tc(const float* __restrict__ A,
                                               const float* __restrict__ B,
                                               __half* __restrict__ C,
                                               int M, int K, int N) {
    __shared__ __align__(16) __half As[GBM][GBK + 8];   // 10240 B
    __shared__ __align__(16) __half Bs[GBK][GBN + 8];   //  4608 B
    __shared__ __align__(16) float  Cst[8][16][20];     // 10240 B

    int tid = threadIdx.x;
    int warp = tid >> 5;
    int lane = tid & 31;
    int wr = warp >> 1;       // 0..3
    int wc = warp & 1;        // 0..1
    int row0 = blockIdx.y * GBM;
    int col0 = blockIdx.x * GBN;

    wmma::fragment<wmma::accumulator, 16, 16, 16, float> acc[2][2];
#pragma unroll
    for (int i = 0; i < 2; i++)
#pragma unroll
        for (int j = 0; j < 2; j++) wmma::fill_fragment(acc[i][j], 0.f);

    for (int k0 = 0; k0 < K; k0 += GBK) {
        // A tile: 128x32 halfs; each thread produces 8 halfs (2 float4 loads), twice
#pragma unroll
        for (int l = 0; l < 2; l++) {
            int idx = tid + l * 256;
            int r = idx >> 2, q = idx & 3;
            int gr = row0 + r;
            float4 v0 = make_float4(0.f, 0.f, 0.f, 0.f);
            float4 v1 = v0;
            if (gr < M) {
                const float* p = A + (size_t)gr * K + k0 + q * 8;
                v0 = *(const float4*)p;
                v1 = *(const float4*)(p + 4);
            }
            __half2 h0 = __floats2half2_rn(v0.x, v0.y);
            __half2 h1 = __floats2half2_rn(v0.z, v0.w);
            __half2 h2 = __floats2half2_rn(v1.x, v1.y);
            __half2 h3 = __floats2half2_rn(v1.z, v1.w);
            uint4 u = make_uint4(*(unsigned*)&h0, *(unsigned*)&h1,
                                 *(unsigned*)&h2, *(unsigned*)&h3);
            *(uint4*)(&As[r][q * 8]) = u;
        }
        // B tile: 32x64 halfs; each thread produces 8 halfs
        {
            int r = tid >> 3, q = tid & 7;
            const float* p = B + (size_t)(k0 + r) * N + col0 + q * 8;
            float4 v0 = *(const float4*)p;
            float4 v1 = *(const float4*)(p + 4);
            __half2 h0 = __floats2half2_rn(v0.x, v0.y);
            __half2 h1 = __floats2half2_rn(v0.z, v0.w);
            __half2 h2 = __floats2half2_rn(v1.x, v1.y);
            __half2 h3 = __floats2half2_rn(v1.z, v1.w);
            uint4 u = make_uint4(*(unsigned*)&h0, *(unsigned*)&h1,
                                 *(unsigned*)&h2, *(unsigned*)&h3);
            *(uint4*)(&Bs[r][q * 8]) = u;
        }
        __syncthreads();
#pragma unroll
        for (int kk = 0; kk < GBK; kk += 16) {
            wmma::fragment<wmma::matrix_a, 16, 16, 16, __half, wmma::row_major> af[2];
            wmma::fragment<wmma::matrix_b, 16, 16, 16, __half, wmma::row_major> bf[2];
#pragma unroll
            for (int i = 0; i < 2; i++)
                wmma::load_matrix_sync(af[i], &As[wr * 32 + i * 16][kk], GBK + 8);
#pragma unroll
            for (int j = 0; j < 2; j++)
                wmma::load_matrix_sync(bf[j], &Bs[kk][wc * 32 + j * 16], GBN + 8);
#pragma unroll
            for (int i = 0; i < 2; i++)
#pragma unroll
                for (int j = 0; j < 2; j++)
                    wmma::mma_sync(acc[i][j], af[i], bf[j], acc[i][j]);
        }
        __syncthreads();
    }
    // epilogue: per-warp fp32 staging -> fp16 global
    int gr0 = row0 + wr * 32;
    int gc0 = col0 + wc * 32;
#pragma unroll
    for (int i = 0; i < 2; i++)
#pragma unroll
        for (int j = 0; j < 2; j++) {
            wmma::store_matrix_sync(&Cst[warp][0][0], acc[i][j], 20, wmma::mem_row_major);
            __syncwarp();
            int gr = gr0 + i * 16, gc = gc0 + j * 16;
#pragma unroll
            for (int e = lane; e < 128; e += 32) {
                int rr = e >> 3, cc = (e & 7) * 2;
                if (gr + rr < M) {
                    __half2 hv = __floats2half2_rn(Cst[warp][rr][cc], Cst[warp][rr][cc + 1]);
                    *(__half2*)(C + (size_t)(gr + rr) * N + gc + cc) = hv;
                }
            }
            __syncwarp();
        }
}

// ---------------- attention logits -------------------------------------------
__global__ void alpha1_kernel(const float* __restrict__ a_src, const float* __restrict__ a_dst) {
    int w = (blockIdx.x * blockDim.x + threadIdx.x) >> 5;
    int lane = threadIdx.x & 31;
    if (w >= NNODES) return;
    int c = lane * 8;
    uint4 u = *(const uint4*)(g_h1h + (long)w * HC + c);
    float2 f0 = __half22float2(*(__half2*)&u.x);
    float2 f1 = __half22float2(*(__half2*)&u.y);
    float2 f2 = __half22float2(*(__half2*)&u.z);
    float2 f3 = __half22float2(*(__half2*)&u.w);
    float4 s0 = *(const float4*)(a_src + c), s1 = *(const float4*)(a_src + c + 4);
    float4 d0 = *(const float4*)(a_dst + c), d1 = *(const float4*)(a_dst + c + 4);
    float ps = f0.x * s0.x + f0.y * s0.y + f1.x * s0.z + f1.y * s0.w
             + f2.x * s1.x + f2.y * s1.y + f3.x * s1.z + f3.y * s1.w;
    float pd = f0.x * d0.x + f0.y * d0.y + f1.x * d0.z + f1.y * d0.w
             + f2.x * d1.x + f2.y * d1.y + f3.x * d1.z + f3.y * d1.w;
#pragma unroll
    for (int off = 4; off; off >>= 1) {
        ps += __shfl_xor_sync(0xffffffffu, ps, off);
        pd += __shfl_xor_sync(0xffffffffu, pd, off);
    }
    if ((lane & 7) == 0) {
        g_als1[w * 4 + (lane >> 3)] = ps;
        g_ald1[w * 4 + (lane >> 3)] = pd;
    }
}

__global__ void alpha2_kernel(const float* __restrict__ a_src, const float* __restrict__ a_dst) {
    int w = (blockIdx.x * blockDim.x + threadIdx.x) >> 5;
    int lane = threadIdx.x & 31;
    if (w >= NNODES) return;
    int c = lane * 2;
    float2 h = __half22float2(*(const __half2*)(g_h2h + (long)w * CC + c));
    float2 sa = *(const float2*)(a_src + c);
    float2 da = *(const float2*)(a_dst + c);
    float ps = h.x * sa.x + h.y * sa.y;
    float pd = h.x * da.x + h.y * da.y;
#pragma unroll
    for (int off = 16; off; off >>= 1) {
        ps += __shfl_xor_sync(0xffffffffu, ps, off);
        pd += __shfl_xor_sync(0xffffffffu, pd, off);
    }
    if (lane == 0) { g_als2[w] = ps; g_ald2[w] = pd; }
}

// ---------------- layer-1 edge softmax + aggregation (warp per dst node) -----
__global__ void __launch_bounds__(256) edge1_kernel(const float* __restrict__ b1) {
    int w = (blockIdx.x * blockDim.x + threadIdx.x) >> 5;
    if (w >= NNODES) return;
    int lane = threadIdx.x & 31;
    int rs = g_rowptr[w], re = g_rowptr[w + 1];
    float4 ad = *(const float4*)(g_ald1 + 4 * w);
    float4 as = *(const float4*)(g_als1 + 4 * w);
    float m0 = lrelu(as.x + ad.x);
    float m1 = lrelu(as.y + ad.y);
    float m2 = lrelu(as.z + ad.z);
    float m3 = lrelu(as.w + ad.w);
    for (int i = rs + lane; i < re; i += 32) {
        int s = g_csrc[i];
        float4 a = *(const float4*)(g_als1 + 4 * s);
        m0 = fmaxf(m0, lrelu(a.x + ad.x));
        m1 = fmaxf(m1, lrelu(a.y + ad.y));
        m2 = fmaxf(m2, lrelu(a.z + ad.z));
        m3 = fmaxf(m3, lrelu(a.w + ad.w));
    }
#pragma unroll
    for (int off = 16; off; off >>= 1) {
        m0 = fmaxf(m0, __shfl_xor_sync(0xffffffffu, m0, off));
        m1 = fmaxf(m1, __shfl_xor_sync(0xffffffffu, m1, off));
        m2 = fmaxf(m2, __shfl_xor_sync(0xffffffffu, m2, off));
        m3 = fmaxf(m3, __shfl_xor_sync(0xffffffffu, m3, off));
    }
    int head = lane >> 3;
    float adh = (head == 0) ? ad.x : (head == 1) ? ad.y : (head == 2) ? ad.z : ad.w;
    float mh  = (head == 0) ? m0  : (head == 1) ? m1  : (head == 2) ? m2  : m3;
    float z = 0.f;
    float acc[8];
#pragma unroll
    for (int q = 0; q < 8; q++) acc[q] = 0.f;
    for (int i = rs; i <= re; ++i) {
        int s = (i < re) ? g_csrc[i] : w;
        float e = g_als1[4 * s + head] + adh;
        e = e > 0.f ? e : NEG * e;
        float wt = __expf(e - mh);
        z += wt;
        uint4 u = *(const uint4*)(g_h1h + (long)s * HC + lane * 8);
        float2 f0 = __half22float2(*(__half2*)&u.x);
        float2 f1 = __half22float2(*(__half2*)&u.y);
        float2 f2 = __half22float2(*(__half2*)&u.z);
        float2 f3 = __half22float2(*(__half2*)&u.w);
        acc[0] += wt * f0.x;  acc[1] += wt * f0.y;
        acc[2] += wt * f1.x;  acc[3] += wt * f1.y;
        acc[4] += wt * f2.x;  acc[5] += wt * f2.y;
        acc[6] += wt * f3.x;  acc[7] += wt * f3.y;
    }
    float inv = 1.f / (z + 1e-16f);
    int c = lane * 8;
    float4 o0 = make_float4(acc[0] * inv + b1[c],     acc[1] * inv + b1[c + 1],
                            acc[2] * inv + b1[c + 2], acc[3] * inv + b1[c + 3]);
    float4 o1 = make_float4(acc[4] * inv + b1[c + 4], acc[5] * inv + b1[c + 5],
                            acc[6] * inv + b1[c + 6], acc[7] * inv + b1[c + 7]);
    *(float4*)(g_out1 + (long)w * HC + c) = o0;
    *(float4*)(g_out1 + (long)w * HC + c + 4) = o1;
}

// ---------------- batchnorm --------------------------------------------------
__global__ void bn_stats_kernel() {
    int c = threadIdx.x;
    float s = 0.f, q = 0.f;
    for (int r = blockIdx.x; r < NNODES; r += gridDim.x) {
        float v = g_out1[(long)r * HC + c];
        s += v;
        q += v * v;
    }
    atomicAdd(&g_bnsum[c], s);
    atomicAdd(&g_bnsq[c], q);
}

__global__ void bn_apply_kernel(const float* __restrict__ gamma, const float* __restrict__ beta) {
    int i = blockIdx.x * blockDim.x + threadIdx.x;
    if (i >= NNODES * HC / 4) return;
    int c = (i & 63) * 4;
    float4 v = *(const float4*)(g_out1 + (long)i * 4);
    float invN = 1.f / (float)NNODES;
    float o[4] = {v.x, v.y, v.z, v.w};
#pragma unroll
    for (int j = 0; j < 4; j++) {
        float mean = g_bnsum[c + j] * invN;
        float var = g_bnsq[c + j] * invN - mean * mean;
        float t = (o[j] - mean) * rsqrtf(var + EPSB) * gamma[c + j] + beta[c + j];
        o[j] = t > 0.f ? t : 0.f;
    }
    *(float4*)(g_h1 + (long)i * 4) = make_float4(o[0], o[1], o[2], o[3]);
}

// ---------------- layer-2 edge softmax + aggregation + pool ------------------
__global__ void __launch_bounds__(256) edge2_kernel(const float* __restrict__ b2,
                                                    const int* __restrict__ batch) {
    int w = (blockIdx.x * blockDim.x + threadIdx.x) >> 5;
    if (w >= NNODES) return;
    int lane = threadIdx.x & 31;
    int rs = g_rowptr[w], re = g_rowptr[w + 1];
    float ald = g_ald2[w];
    float m = lrelu(g_als2[w] + ald);
    for (int i = rs + lane; i < re; i += 32)
        m = fmaxf(m, lrelu(g_als2[g_csrc[i]] + ald));
#pragma unroll
    for (int off = 16; off; off >>= 1)
        m = fmaxf(m, __shfl_xor_sync(0xffffffffu, m, off));
    float z = 0.f, a0 = 0.f, a1 = 0.f;
    for (int i = rs; i <= re; ++i) {
        int s = (i < re) ? g_csrc[i] : w;
        float e = g_als2[s] + ald;
        e = e > 0.f ? e : NEG * e;
        float wt = __expf(e - m);
        z += wt;
        float2 h = __half22float2(*(const __half2*)(g_h2h + (long)s * CC + lane * 2));
        a0 += wt * h.x;
        a1 += wt * h.y;
    }
    float inv = 1.f / (z + 1e-16f);
    int c = lane * 2;
    float v0 = fmaxf(a0 * inv + b2[c], 0.f);
    float v1 = fmaxf(a1 * inv + b2[c + 1], 0.f);
    int g = batch[w];
    atomicAdd(&g_pool[g * CC + c], v0);
    atomicAdd(&g_pool[g * CC + c + 1], v1);
    if (lane == 0) atomicAdd(&g_cnt[g], 1.f);
}

// ---------------- classifier -------------------------------------------------
__global__ void cls_kernel(const float* __restrict__ cW1, const float* __restrict__ cb1,
                           const float* __restrict__ cW2, const float* __restrict__ cb2,
                           float* __restrict__ out) {
    int g = blockIdx.x;
    __shared__ float p[CC];
    __shared__ float hid[CC / 2];
    int t = threadIdx.x;
    float cnt = fmaxf(g_cnt[g], 1.f);
    p[t] = g_pool[g * CC + t] / cnt;
    __syncthreads();
    if (t < 32) {
        float s = cb1[t];
#pragma unroll
        for (int c = 0; c < CC; c++) s += p[c] * cW1[c * 32 + t];
        hid[t] = fmaxf(s, 0.f);
    }
    __syncthreads();
    if (t < NOUT) {
        float s = cb2[t];
#pragma unroll
        for (int j = 0; j < 32; j++) s += hid[j] * cW2[j * NOUT + t];
        out[g * NOUT + t] = s;
    }
}

// ---------------- launch -----------------------------------------------------
extern "C" void kernel_launch(void* const* d_in, const int* in_sizes, int n_in,
                              void* d_out, int out_size) {
    const float* x     = (const float*)d_in[0];
    const int*   ei    = (const int*)d_in[1];
    const int*   batch = (const int*)d_in[2];
    const float* W1    = (const float*)d_in[3];
    const float* as1   = (const float*)d_in[4];
    const float* ad1   = (const float*)d_in[5];
    const float* b1    = (const float*)d_in[6];
    const float* gamma = (const float*)d_in[7];
    const float* beta  = (const float*)d_in[8];
    const float* W2    = (const float*)d_in[9];
    const float* as2   = (const float*)d_in[10];
    const float* ad2   = (const float*)d_in[11];
    const float* b2    = (const float*)d_in[12];
    const float* cW1   = (const float*)d_in[13];
    const float* cb1   = (const float*)d_in[14];
    const float* cW2   = (const float*)d_in[15];
    const float* cb2   = (const float*)d_in[16];
    float* out = (float*)d_out;

    const int* src = ei;
    const int* dst = ei + NEDGES;

    float *h1p;
    __half *h1hp, *h2hp;
    cudaGetSymbolAddress((void**)&h1p, g_h1);
    cudaGetSymbolAddress((void**)&h1hp, g_h1h);
    cudaGetSymbolAddress((void**)&h2hp, g_h2h);

    const int EB4 = (NEDGES / 4 + 255) / 256;
    const int WB = (NNODES * 32 + 255) / 256;
    const int GY = (NNODES + GBM - 1) / GBM;   // 391

    zero_kernel<<<(NNODES + 255) / 256, 256>>>();
    hist_kernel<<<EB4, 256>>>(dst);
    scanA_kernel<<<NB_SCAN, 1024>>>();
    scanB_kernel<<<1, 32>>>();
    scanC_kernel<<<NB_SCAN, 1024>>>();
    scatter_kernel<<<EB4, 256>>>(src, dst);

    // layer 1
    gemm_tc<<<dim3(HC / GBN, GY), 256>>>(x, W1, h1hp, NNODES, DIN, HC);
    alpha1_kernel<<<WB, 256>>>(as1, ad1);
    edge1_kernel<<<WB, 256>>>(b1);
    bn_stats_kernel<<<256, 256>>>();
    bn_apply_kernel<<<(NNODES * HC / 4 + 255) / 256, 256>>>(gamma, beta);

    // layer 2
    gemm_tc<<<dim3(CC / GBN, GY), 256>>>(h1p, W2, h2hp, NNODES, HC, CC);
    alpha2_kernel<<<WB, 256>>>(as2, ad2);
    edge2_kernel<<<WB, 256>>>(b2, batch);

    // classifier
    cls_kernel<<<NG, 64>>>(cW1, cb1, cW2, cb2, out);
}